// round 4
// baseline (speedup 1.0000x reference)
#include <cuda_runtime.h>
#include <math.h>

// Problem constants (fixed by the dataset)
#define NN 50000
#define NE 600000
#define C  128
#define KTOT 1280        // 10 blocks of 128: 9 PNA feature blocks + root(x)

// ---------------- scratch (device globals: allocation-free rule) -------------
__device__ __align__(16) float g_Asum[(size_t)NN * C];   // 25.6 MB
__device__ __align__(16) float g_Amax[(size_t)NN * C];   // 25.6 MB
__device__ __align__(16) int   g_deg[NN];
__device__ __align__(16) int   g_off[NN + 1];
__device__ __align__(16) int   g_cur[NN];
__device__ __align__(16) int   g_bucket[NE];
__device__ __align__(16) float g_amp[NN];
__device__ __align__(16) float g_att[NN];
__device__ __align__(16) float g_minv[NN];
__device__ __align__(16) float g_Bt[KTOT * C];           // [k][o] combined weights
__device__ float g_ref;
__device__ int   g_is64;

// ---------------- phase 0: edge_index dtype autodetect ----------------
// int64 little-endian with values < 50000 -> every odd 32-bit word is 0.
// int32 -> odd words are live edge indices (OR over 128 samples ~never 0).
__global__ void k_detect(const int* __restrict__ ei32) {
    if (threadIdx.x == 0 && blockIdx.x == 0) {
        int odd_or = 0;
        for (int i = 0; i < 128; i++) odd_or |= ei32[2 * i + 1];
        g_is64 = (odd_or == 0) ? 1 : 0;
    }
}

__device__ __forceinline__ int load_edge(const void* ei, int idx) {
    int v;
    if (g_is64) v = (int)((const long long*)ei)[idx];
    else        v = ((const int*)ei)[idx];
    // defensive clamp: any residual dtype/layout mismatch must yield a finite
    // rel_err rather than an address-space trap.
    return min(max(v, 0), NN - 1);
}

// ---------------- phase 1: degree count ----------------
__global__ void k_zero_deg() {
    int i = blockIdx.x * blockDim.x + threadIdx.x;
    if (i < NN) g_deg[i] = 0;
}

__global__ void k_count(const void* __restrict__ ei) {
    int i = blockIdx.x * blockDim.x + threadIdx.x;
    if (i < NE) {
        int dst = load_edge(ei, NE + i);
        atomicAdd(&g_deg[dst], 1);
    }
}

// single-block exclusive scan of degrees -> offsets + cursors; also computes
// degree_reference = max(mean(log1p(deg+1)), 1)
__global__ void k_scan() {
    __shared__ int   ps[1024];
    __shared__ float ls[1024];
    int t = threadIdx.x;
    const int CH = (NN + 1023) / 1024;   // 49
    int beg = t * CH;
    int end = min(beg + CH, NN);
    int s = 0;
    float lg = 0.f;
    for (int i = beg; i < end; i++) {
        int d = g_deg[i];
        s += d;
        lg += log1pf((float)d + 1.0f);
    }
    ps[t] = s;
    ls[t] = lg;
    __syncthreads();
    // Hillis-Steele inclusive scan
    for (int off = 1; off < 1024; off <<= 1) {
        int v = 0;
        if (t >= off) v = ps[t - off];
        __syncthreads();
        if (t >= off) ps[t] += v;
        __syncthreads();
    }
    int run = (t == 0) ? 0 : ps[t - 1];
    for (int i = beg; i < end; i++) {
        g_off[i] = run;
        g_cur[i] = run;
        run += g_deg[i];
    }
    if (t == 1023) g_off[NN] = ps[1023];
    __syncthreads();
    // reduce log-degree sum
    for (int off = 512; off > 0; off >>= 1) {
        if (t < off) ls[t] += ls[t + off];
        __syncthreads();
    }
    if (t == 0) g_ref = fmaxf(ls[0] / (float)NN, 1.0f);
}

__global__ void k_scatter(const void* __restrict__ ei) {
    int i = blockIdx.x * blockDim.x + threadIdx.x;
    if (i < NE) {
        int src = load_edge(ei, i);
        int dst = load_edge(ei, NE + i);
        int pos = atomicAdd(&g_cur[dst], 1);
        if (pos >= 0 && pos < NE) g_bucket[pos] = src;
    }
}

// ---------------- phase 2: per-node gather-reduce (sum + max) ----------------
__global__ void k_agg(const float* __restrict__ x) {
    int node = blockIdx.x;
    int t = threadIdx.x;
    int beg = g_off[node], end = g_off[node + 1];
    int deg = end - beg;
    __shared__ int lst[128];
    float s = 0.f;
    float mx = -1e30f;
    for (int base = beg; base < end; base += 128) {
        int cnt = min(128, end - base);
        if (t < cnt) lst[t] = g_bucket[base + t];
        __syncthreads();
        for (int j = 0; j < cnt; j++) {
            float v = x[(size_t)lst[j] * C + t];
            s += v;
            mx = fmaxf(mx, v);
        }
        __syncthreads();
    }
    size_t o = (size_t)node * C + t;
    g_Asum[o] = s;
    g_Amax[o] = (deg > 0) ? mx : 0.f;
    if (t == 0) {
        float dt = log1pf((float)deg + 1.0f);
        float rf = g_ref;
        g_amp[node]  = dt / rf;
        g_att[node]  = rf / fmaxf(dt, 1e-6f);
        g_minv[node] = 1.0f / fmaxf((float)deg, 1.0f);
    }
}

// ---------------- phase 3a: build transposed weight matrix [KTOT][C] ---------
// k < 1152 -> W_msg[o, k]; k >= 1152 -> W_root[o, k-1152]
__global__ void k_buildB(const float* __restrict__ Wmsg,
                         const float* __restrict__ Wroot) {
    int idx = blockIdx.x * blockDim.x + threadIdx.x;
    if (idx < KTOT * C) {
        int kk = idx / C;
        int o  = idx % C;
        float v = (kk < 1152) ? Wmsg[(size_t)o * 1152 + kk]
                              : Wroot[(size_t)o * C + (kk - 1152)];
        g_Bt[idx] = v;
    }
}

// ---------------- phase 3b: fused GEMM ----------------
// out[m,o] = sum_k Agen[m,k] * Bt[k,o] + b_msg[o] + b_root[o]
// Agen generated on the fly: block b = k/128 selects base + per-row coefficient
//   b: 0=sum  1=sum*amp  2=sum*att  3=mean  4=mean*amp  5=mean*att
//      6=max  7=max*amp  8=max*att  9=x
#define BM 128
#define BN 128
#define BK 16

__global__ void __launch_bounds__(256, 2)
k_gemm(const float* __restrict__ x,
       const float* __restrict__ bmsg,
       const float* __restrict__ broot,
       float* __restrict__ out) {
    __shared__ float As[BK][BM + 4];
    __shared__ float Bs[BK][BN];
    __shared__ float sAmp[BM], sAtt[BM], sMinv[BM];
    __shared__ float sBias[BN];

    int tid = threadIdx.x;
    int m0 = blockIdx.x * BM;

    if (tid < BM) {
        int m = m0 + tid;
        if (m < NN) {
            sAmp[tid]  = g_amp[m];
            sAtt[tid]  = g_att[m];
            sMinv[tid] = g_minv[m];
        } else {
            sAmp[tid] = 0.f; sAtt[tid] = 0.f; sMinv[tid] = 0.f;
        }
    } else {
        int o = tid - BM;
        sBias[o] = bmsg[o] + broot[o];
    }
    __syncthreads();

    float acc[8][8];
#pragma unroll
    for (int i = 0; i < 8; i++)
#pragma unroll
        for (int j = 0; j < 8; j++) acc[i][j] = 0.f;

    const int lr = tid >> 1;           // A loader: row in tile (0..127)
    const int lk = (tid & 1) * 8;      // A loader: k sub-offset (0 or 8)
    const int brow = tid >> 4;         // B loader: k row (0..15)
    const int bcol = (tid & 15) * 8;   // B loader: col (0..120)
    const int tx = tid & 15;           // compute: n group
    const int ty = tid >> 4;           // compute: m group

    for (int kt = 0; kt < KTOT / BK; kt++) {
        int k0 = kt * BK;
        int b = k0 >> 7;
        // ---- load + generate A tile ----
        {
            int m = m0 + lr;
            float ca = sAmp[lr], ct = sAtt[lr], cm = sMinv[lr];
            const float* base = (b < 6) ? g_Asum : ((b < 9) ? g_Amax : x);
            int sc = (b < 6) ? (b % 3) : ((b < 9) ? (b - 6) : 0);
            float coef = (sc == 0) ? 1.f : ((sc == 1) ? ca : ct);
            if (b >= 3 && b < 6) coef *= cm;
            if (b == 9) coef = 1.f;

            int col = (k0 & 127) + lk;
            const float* p = base + (size_t)min(m, NN - 1) * C + col;
#pragma unroll
            for (int q = 0; q < 8; q++) {
                float v = (m < NN) ? p[q] : 0.f;
                As[lk + q][lr] = v * coef;
            }
        }
        // ---- load B tile ----
        {
            const float* p = g_Bt + (size_t)(k0 + brow) * C + bcol;
#pragma unroll
            for (int q = 0; q < 8; q++) Bs[brow][bcol + q] = p[q];
        }
        __syncthreads();
        // ---- compute: 8x8 per thread ----
#pragma unroll
        for (int k = 0; k < BK; k++) {
            float av[8], bv[8];
#pragma unroll
            for (int q = 0; q < 8; q++) av[q] = As[k][ty * 8 + q];
#pragma unroll
            for (int q = 0; q < 8; q++) bv[q] = Bs[k][tx * 8 + q];
#pragma unroll
            for (int i = 0; i < 8; i++)
#pragma unroll
                for (int j = 0; j < 8; j++)
                    acc[i][j] = fmaf(av[i], bv[j], acc[i][j]);
        }
        __syncthreads();
    }

    // ---- epilogue ----
    int o0 = tx * 8;
#pragma unroll
    for (int i = 0; i < 8; i++) {
        int m = m0 + ty * 8 + i;
        if (m < NN) {
            float* po = out + (size_t)m * C + o0;
#pragma unroll
            for (int j = 0; j < 8; j++)
                po[j] = acc[i][j] + sBias[o0 + j];
        }
    }
}

// ---------------- launch ----------------
extern "C" void kernel_launch(void* const* d_in, const int* in_sizes, int n_in,
                              void* d_out, int out_size) {
    const float* x     = (const float*)d_in[0];
    const void*  ei    = d_in[1];
    const float* Wmsg  = (const float*)d_in[2];
    const float* bmsg  = (const float*)d_in[3];
    const float* Wroot = (const float*)d_in[4];
    const float* broot = (const float*)d_in[5];
    float*       out   = (float*)d_out;

    k_detect<<<1, 32>>>((const int*)ei);
    k_zero_deg<<<(NN + 255) / 256, 256>>>();
    k_count<<<(NE + 255) / 256, 256>>>(ei);
    k_scan<<<1, 1024>>>();
    k_scatter<<<(NE + 255) / 256, 256>>>(ei);
    k_agg<<<NN, 128>>>(x);
    k_buildB<<<(KTOT * C + 255) / 256, 256>>>(Wmsg, Wroot);
    k_gemm<<<(NN + BM - 1) / BM, 256>>>(x, bmsg, broot, out);
}

// round 5
// speedup vs baseline: 1.0423x; 1.0423x over previous
#include <cuda_runtime.h>
#include <math.h>

// Problem constants (fixed by the dataset)
#define NN 50000
#define NE 600000
#define C  128
#define KTOT 1280        // 10 blocks of 128: 9 PNA feature blocks + root(x)

#define SB 256
#define NB ((NN + SB - 1) / SB)   // 196 scan blocks

typedef unsigned long long ull;

// ---------------- scratch (device globals: allocation-free rule) -------------
__device__ __align__(16) float g_Asum[(size_t)NN * C];   // 25.6 MB
__device__ __align__(16) float g_Amax[(size_t)NN * C];   // 25.6 MB
__device__ __align__(16) int   g_deg[NN];
__device__ __align__(16) int   g_off[NN + 1];
__device__ __align__(16) int   g_cur[NN];
__device__ __align__(16) int   g_bucket[NE];
__device__ __align__(16) float g_amp[NN];
__device__ __align__(16) float g_att[NN];
__device__ __align__(16) float g_minv[NN];
__device__ __align__(16) float g_Bt[KTOT * C];           // [k][o] combined weights
__device__ __align__(16) int   g_psum[NB];
__device__ __align__(16) float g_plog[NB];
__device__ __align__(16) int   g_pbase[NB];
__device__ float g_ref;
__device__ int   g_is64;

// ---------------- phase 0: edge_index dtype autodetect ----------------
__global__ void k_detect(const int* __restrict__ ei32) {
    if (threadIdx.x == 0 && blockIdx.x == 0) {
        int odd_or = 0;
        for (int i = 0; i < 128; i++) odd_or |= ei32[2 * i + 1];
        g_is64 = (odd_or == 0) ? 1 : 0;
    }
}

__device__ __forceinline__ int load_edge(const void* ei, int idx) {
    int v;
    if (g_is64) v = (int)((const long long*)ei)[idx];
    else        v = ((const int*)ei)[idx];
    return min(max(v, 0), NN - 1);
}

// ---------------- phase 1: degree count ----------------
__global__ void k_zero_deg() {
    int i = blockIdx.x * blockDim.x + threadIdx.x;
    if (i < NN) g_deg[i] = 0;
}

__global__ void k_count(const void* __restrict__ ei) {
    int i = blockIdx.x * blockDim.x + threadIdx.x;
    if (i < NE) {
        int dst = load_edge(ei, NE + i);
        atomicAdd(&g_deg[dst], 1);
    }
}

// ---------------- multi-block scan: partials -> tiny scan -> write ----------
__global__ void k_part() {
    __shared__ int   si[SB];
    __shared__ float sf[SB];
    int t = threadIdx.x;
    int node = blockIdx.x * SB + t;
    int d = (node < NN) ? g_deg[node] : 0;
    si[t] = d;
    sf[t] = (node < NN) ? log1pf((float)d + 1.0f) : 0.f;
    __syncthreads();
    for (int off = SB / 2; off > 0; off >>= 1) {
        if (t < off) { si[t] += si[t + off]; sf[t] += sf[t + off]; }
        __syncthreads();
    }
    if (t == 0) { g_psum[blockIdx.x] = si[0]; g_plog[blockIdx.x] = sf[0]; }
}

__global__ void k_scan2() {
    __shared__ int   ps[SB];
    __shared__ float ls[SB];
    int t = threadIdx.x;
    int v = (t < NB) ? g_psum[t] : 0;
    float lg = (t < NB) ? g_plog[t] : 0.f;
    ps[t] = v;
    ls[t] = lg;
    __syncthreads();
    for (int off = 1; off < SB; off <<= 1) {
        int a = 0;
        if (t >= off) a = ps[t - off];
        __syncthreads();
        if (t >= off) ps[t] += a;
        __syncthreads();
    }
    if (t < NB) g_pbase[t] = ps[t] - v;   // exclusive
    if (t == SB - 1) g_off[NN] = ps[SB - 1];
    // reduce log sum
    for (int off = SB / 2; off > 0; off >>= 1) {
        if (t < off) ls[t] += ls[t + off];
        __syncthreads();
    }
    if (t == 0) g_ref = fmaxf(ls[0] / (float)NN, 1.0f);
}

__global__ void k_write() {
    __shared__ int ps[SB];
    int t = threadIdx.x;
    int node = blockIdx.x * SB + t;
    int d = (node < NN) ? g_deg[node] : 0;
    ps[t] = d;
    __syncthreads();
    for (int off = 1; off < SB; off <<= 1) {
        int a = 0;
        if (t >= off) a = ps[t - off];
        __syncthreads();
        if (t >= off) ps[t] += a;
        __syncthreads();
    }
    if (node < NN) {
        int off = g_pbase[blockIdx.x] + ps[t] - d;  // exclusive
        g_off[node] = off;
        g_cur[node] = off;
    }
}

__global__ void k_scatter(const void* __restrict__ ei) {
    int i = blockIdx.x * blockDim.x + threadIdx.x;
    if (i < NE) {
        int src = load_edge(ei, i);
        int dst = load_edge(ei, NE + i);
        int pos = atomicAdd(&g_cur[dst], 1);
        if (pos >= 0 && pos < NE) g_bucket[pos] = src;
    }
}

// ---------------- phase 2: per-node gather-reduce (sum + max) ----------------
__global__ void k_agg(const float* __restrict__ x) {
    int node = blockIdx.x;
    int t = threadIdx.x;
    int beg = g_off[node], end = g_off[node + 1];
    int deg = end - beg;
    __shared__ int lst[128];
    float s = 0.f;
    float mx = -1e30f;
    for (int base = beg; base < end; base += 128) {
        int cnt = min(128, end - base);
        if (t < cnt) lst[t] = g_bucket[base + t];
        __syncthreads();
        int j = 0;
        for (; j + 4 <= cnt; j += 4) {
            float v0 = x[(size_t)lst[j + 0] * C + t];
            float v1 = x[(size_t)lst[j + 1] * C + t];
            float v2 = x[(size_t)lst[j + 2] * C + t];
            float v3 = x[(size_t)lst[j + 3] * C + t];
            s += v0 + v1 + v2 + v3;
            mx = fmaxf(mx, fmaxf(fmaxf(v0, v1), fmaxf(v2, v3)));
        }
        for (; j < cnt; j++) {
            float v = x[(size_t)lst[j] * C + t];
            s += v;
            mx = fmaxf(mx, v);
        }
        __syncthreads();
    }
    size_t o = (size_t)node * C + t;
    g_Asum[o] = s;
    g_Amax[o] = (deg > 0) ? mx : 0.f;
    if (t == 0) {
        float dt = log1pf((float)deg + 1.0f);
        float rf = g_ref;
        g_amp[node]  = dt / rf;
        g_att[node]  = rf / fmaxf(dt, 1e-6f);
        g_minv[node] = 1.0f / fmaxf((float)deg, 1.0f);
    }
}

// ---------------- phase 3a: build transposed weight matrix [KTOT][C] ---------
__global__ void k_buildB(const float* __restrict__ Wmsg,
                         const float* __restrict__ Wroot) {
    int idx = blockIdx.x * blockDim.x + threadIdx.x;
    if (idx < KTOT * C) {
        int kk = idx / C;
        int o  = idx % C;
        float v = (kk < 1152) ? Wmsg[(size_t)o * 1152 + kk]
                              : Wroot[(size_t)o * C + (kk - 1152)];
        g_Bt[idx] = v;
    }
}

// ---------------- phase 3b: fused GEMM (packed f32x2 inner loop) -------------
// out[m,o] = sum_k Agen[m,k] * Bt[k,o] + b_msg[o] + b_root[o]
//   b: 0=sum  1=sum*amp  2=sum*att  3=mean  4=mean*amp  5=mean*att
//      6=max  7=max*amp  8=max*att  9=x
#define BM 128
#define BN 128
#define BK 16

__global__ void __launch_bounds__(256, 2)
k_gemm(const float* __restrict__ x,
       const float* __restrict__ bmsg,
       const float* __restrict__ broot,
       float* __restrict__ out) {
    __shared__ float As[BK][BM + 4];
    __shared__ float Bs[BK][BN];
    __shared__ float sAmp[BM], sAtt[BM], sMinv[BM];
    __shared__ float sBias[BN];

    int tid = threadIdx.x;
    int m0 = blockIdx.x * BM;

    if (tid < BM) {
        int m = m0 + tid;
        if (m < NN) {
            sAmp[tid]  = g_amp[m];
            sAtt[tid]  = g_att[m];
            sMinv[tid] = g_minv[m];
        } else {
            sAmp[tid] = 0.f; sAtt[tid] = 0.f; sMinv[tid] = 0.f;
        }
    } else {
        int o = tid - BM;
        sBias[o] = bmsg[o] + broot[o];
    }
    __syncthreads();

    ull acc[8][4];
#pragma unroll
    for (int i = 0; i < 8; i++)
#pragma unroll
        for (int j = 0; j < 4; j++) acc[i][j] = 0ull;

    const int lr = tid >> 1;           // A loader: row in tile (0..127)
    const int lk = (tid & 1) * 8;      // A loader: k sub-offset (0 or 8)
    const int brow = tid >> 4;         // B loader: k row (0..15)
    const int bcol = (tid & 15) * 8;   // B loader: col (0..120)
    const int tx = tid & 15;           // compute: n group
    const int ty = tid >> 4;           // compute: m group

    for (int kt = 0; kt < KTOT / BK; kt++) {
        int k0 = kt * BK;
        int b = k0 >> 7;
        // ---- load + generate A tile ----
        {
            int m = m0 + lr;
            float ca = sAmp[lr], ct = sAtt[lr], cm = sMinv[lr];
            const float* base = (b < 6) ? g_Asum : ((b < 9) ? g_Amax : x);
            int sc = (b < 6) ? (b % 3) : ((b < 9) ? (b - 6) : 0);
            float coef = (sc == 0) ? 1.f : ((sc == 1) ? ca : ct);
            if (b >= 3 && b < 6) coef *= cm;
            if (b == 9) coef = 1.f;

            int col = (k0 & 127) + lk;
            const float* p = base + (size_t)min(m, NN - 1) * C + col;
            float4 v0, v1;
            if (m < NN) {
                v0 = *(const float4*)(p);
                v1 = *(const float4*)(p + 4);
            } else {
                v0 = make_float4(0.f, 0.f, 0.f, 0.f);
                v1 = v0;
            }
            As[lk + 0][lr] = v0.x * coef;
            As[lk + 1][lr] = v0.y * coef;
            As[lk + 2][lr] = v0.z * coef;
            As[lk + 3][lr] = v0.w * coef;
            As[lk + 4][lr] = v1.x * coef;
            As[lk + 5][lr] = v1.y * coef;
            As[lk + 6][lr] = v1.z * coef;
            As[lk + 7][lr] = v1.w * coef;
        }
        // ---- load B tile ----
        {
            const float4* p = (const float4*)(g_Bt + (size_t)(k0 + brow) * C + bcol);
            float4 w0 = p[0];
            float4 w1 = p[1];
            *(float4*)&Bs[brow][bcol]     = w0;
            *(float4*)&Bs[brow][bcol + 4] = w1;
        }
        __syncthreads();
        // ---- compute: 8x8 per thread, packed f32x2 along n ----
#pragma unroll
        for (int k = 0; k < BK; k++) {
            const float4 a0 = *(const float4*)(&As[k][ty * 8]);
            const float4 a1 = *(const float4*)(&As[k][ty * 8 + 4]);
            const ull* bp = (const ull*)(&Bs[k][tx * 8]);
            ull b0 = bp[0], b1 = bp[1], b2 = bp[2], b3 = bp[3];
            float av[8] = {a0.x, a0.y, a0.z, a0.w, a1.x, a1.y, a1.z, a1.w};
#pragma unroll
            for (int i = 0; i < 8; i++) {
                ull aa;
                unsigned int ai = __float_as_uint(av[i]);
                asm("mov.b64 %0, {%1, %1};" : "=l"(aa) : "r"(ai));
                asm("fma.rn.f32x2 %0, %1, %2, %0;" : "+l"(acc[i][0]) : "l"(aa), "l"(b0));
                asm("fma.rn.f32x2 %0, %1, %2, %0;" : "+l"(acc[i][1]) : "l"(aa), "l"(b1));
                asm("fma.rn.f32x2 %0, %1, %2, %0;" : "+l"(acc[i][2]) : "l"(aa), "l"(b2));
                asm("fma.rn.f32x2 %0, %1, %2, %0;" : "+l"(acc[i][3]) : "l"(aa), "l"(b3));
            }
        }
        __syncthreads();
    }

    // ---- epilogue ----
    int o0 = tx * 8;
#pragma unroll
    for (int i = 0; i < 8; i++) {
        int m = m0 + ty * 8 + i;
        if (m < NN) {
            float r[8];
#pragma unroll
            for (int j = 0; j < 4; j++) {
                unsigned int lo, hi;
                asm("mov.b64 {%0, %1}, %2;" : "=r"(lo), "=r"(hi) : "l"(acc[i][j]));
                r[2 * j]     = __uint_as_float(lo);
                r[2 * j + 1] = __uint_as_float(hi);
            }
#pragma unroll
            for (int q = 0; q < 8; q++) r[q] += sBias[o0 + q];
            float4* po = (float4*)(&out[(size_t)m * C + o0]);
            po[0] = make_float4(r[0], r[1], r[2], r[3]);
            po[1] = make_float4(r[4], r[5], r[6], r[7]);
        }
    }
}

// ---------------- launch ----------------
extern "C" void kernel_launch(void* const* d_in, const int* in_sizes, int n_in,
                              void* d_out, int out_size) {
    const float* x     = (const float*)d_in[0];
    const void*  ei    = d_in[1];
    const float* Wmsg  = (const float*)d_in[2];
    const float* bmsg  = (const float*)d_in[3];
    const float* Wroot = (const float*)d_in[4];
    const float* broot = (const float*)d_in[5];
    float*       out   = (float*)d_out;

    k_detect<<<1, 32>>>((const int*)ei);
    k_zero_deg<<<(NN + 255) / 256, 256>>>();
    k_count<<<(NE + 255) / 256, 256>>>(ei);
    k_part<<<NB, SB>>>();
    k_scan2<<<1, SB>>>();
    k_write<<<NB, SB>>>();
    k_scatter<<<(NE + 255) / 256, 256>>>(ei);
    k_agg<<<NN, 128>>>(x);
    k_buildB<<<(KTOT * C + 255) / 256, 256>>>(Wmsg, Wroot);
    k_gemm<<<(NN + BM - 1) / BM, 256>>>(x, bmsg, broot, out);
}

// round 7
// speedup vs baseline: 2.7875x; 2.6744x over previous
#include <cuda_runtime.h>
#include <cuda_bf16.h>
#include <math.h>
#include <cstdint>

// Problem constants (fixed by the dataset)
#define NN 50000
#define NE 600000
#define C  128
#define KTOT 1280        // 10 blocks of 128: 9 PNA feature blocks + root(x)
#define NKB  (KTOT / 64) // 20 k-blocks of 64

#define SB 256
#define NB ((NN + SB - 1) / SB)

typedef unsigned long long ull;

// ---------------- scratch (device globals: allocation-free rule) -------------
__device__ __align__(16) float g_Asum[(size_t)NN * C];
__device__ __align__(16) float g_Amax[(size_t)NN * C];
__device__ __align__(16) int   g_deg[NN];
__device__ __align__(16) int   g_off[NN + 1];
__device__ __align__(16) int   g_cur[NN];
__device__ __align__(16) int   g_bucket[NE];
__device__ __align__(16) float g_amp[NN];
__device__ __align__(16) float g_att[NN];
__device__ __align__(16) float g_minv[NN];
// pre-split B tiles: [NKB][128 n-rows][64 k-cols] bf16, linear
__device__ __align__(16) __nv_bfloat16 g_Bhi[NKB * 128 * 64];
__device__ __align__(16) __nv_bfloat16 g_Blo[NKB * 128 * 64];
__device__ __align__(16) int   g_psum[NB];
__device__ __align__(16) float g_plog[NB];
__device__ __align__(16) int   g_pbase[NB];
__device__ float g_ref;
__device__ int   g_is64;

// ---------------- phase 0: edge_index dtype autodetect ----------------
__global__ void k_detect(const int* __restrict__ ei32) {
    if (threadIdx.x == 0 && blockIdx.x == 0) {
        int odd_or = 0;
        for (int i = 0; i < 128; i++) odd_or |= ei32[2 * i + 1];
        g_is64 = (odd_or == 0) ? 1 : 0;
    }
}

__device__ __forceinline__ int load_edge(const void* ei, int idx) {
    int v;
    if (g_is64) v = (int)((const long long*)ei)[idx];
    else        v = ((const int*)ei)[idx];
    return min(max(v, 0), NN - 1);
}

// ---------------- phase 1: degree count ----------------
__global__ void k_zero_deg() {
    int i = blockIdx.x * blockDim.x + threadIdx.x;
    if (i < NN) g_deg[i] = 0;
}

__global__ void k_count(const void* __restrict__ ei) {
    int i = blockIdx.x * blockDim.x + threadIdx.x;
    if (i < NE) {
        int dst = load_edge(ei, NE + i);
        atomicAdd(&g_deg[dst], 1);
    }
}

// ---------------- multi-block scan ----------------
__global__ void k_part() {
    __shared__ int   si[SB];
    __shared__ float sf[SB];
    int t = threadIdx.x;
    int node = blockIdx.x * SB + t;
    int d = (node < NN) ? g_deg[node] : 0;
    si[t] = d;
    sf[t] = (node < NN) ? log1pf((float)d + 1.0f) : 0.f;
    __syncthreads();
    for (int off = SB / 2; off > 0; off >>= 1) {
        if (t < off) { si[t] += si[t + off]; sf[t] += sf[t + off]; }
        __syncthreads();
    }
    if (t == 0) { g_psum[blockIdx.x] = si[0]; g_plog[blockIdx.x] = sf[0]; }
}

__global__ void k_scan2() {
    __shared__ int   ps[SB];
    __shared__ float ls[SB];
    int t = threadIdx.x;
    int v = (t < NB) ? g_psum[t] : 0;
    float lg = (t < NB) ? g_plog[t] : 0.f;
    ps[t] = v;
    ls[t] = lg;
    __syncthreads();
    for (int off = 1; off < SB; off <<= 1) {
        int a = 0;
        if (t >= off) a = ps[t - off];
        __syncthreads();
        if (t >= off) ps[t] += a;
        __syncthreads();
    }
    if (t < NB) g_pbase[t] = ps[t] - v;
    if (t == SB - 1) g_off[NN] = ps[SB - 1];
    for (int off = SB / 2; off > 0; off >>= 1) {
        if (t < off) ls[t] += ls[t + off];
        __syncthreads();
    }
    if (t == 0) g_ref = fmaxf(ls[0] / (float)NN, 1.0f);
}

__global__ void k_write() {
    __shared__ int ps[SB];
    int t = threadIdx.x;
    int node = blockIdx.x * SB + t;
    int d = (node < NN) ? g_deg[node] : 0;
    ps[t] = d;
    __syncthreads();
    for (int off = 1; off < SB; off <<= 1) {
        int a = 0;
        if (t >= off) a = ps[t - off];
        __syncthreads();
        if (t >= off) ps[t] += a;
        __syncthreads();
    }
    if (node < NN) {
        int off = g_pbase[blockIdx.x] + ps[t] - d;
        g_off[node] = off;
        g_cur[node] = off;
    }
}

__global__ void k_scatter(const void* __restrict__ ei) {
    int i = blockIdx.x * blockDim.x + threadIdx.x;
    if (i < NE) {
        int src = load_edge(ei, i);
        int dst = load_edge(ei, NE + i);
        int pos = atomicAdd(&g_cur[dst], 1);
        if (pos >= 0 && pos < NE) g_bucket[pos] = src;
    }
}

// ---------------- phase 2: per-node gather-reduce (sum + max) ----------------
__global__ void k_agg(const float* __restrict__ x) {
    int node = blockIdx.x;
    int t = threadIdx.x;
    int beg = g_off[node], end = g_off[node + 1];
    int deg = end - beg;
    __shared__ int lst[128];
    float s = 0.f;
    float mx = -1e30f;
    for (int base = beg; base < end; base += 128) {
        int cnt = min(128, end - base);
        if (t < cnt) lst[t] = g_bucket[base + t];
        __syncthreads();
        int j = 0;
        for (; j + 4 <= cnt; j += 4) {
            float v0 = x[(size_t)lst[j + 0] * C + t];
            float v1 = x[(size_t)lst[j + 1] * C + t];
            float v2 = x[(size_t)lst[j + 2] * C + t];
            float v3 = x[(size_t)lst[j + 3] * C + t];
            s += v0 + v1 + v2 + v3;
            mx = fmaxf(mx, fmaxf(fmaxf(v0, v1), fmaxf(v2, v3)));
        }
        for (; j < cnt; j++) {
            float v = x[(size_t)lst[j] * C + t];
            s += v;
            mx = fmaxf(mx, v);
        }
        __syncthreads();
    }
    size_t o = (size_t)node * C + t;
    g_Asum[o] = s;
    g_Amax[o] = (deg > 0) ? mx : 0.f;
    if (t == 0) {
        float dt = log1pf((float)deg + 1.0f);
        float rf = g_ref;
        g_amp[node]  = dt / rf;
        g_att[node]  = rf / fmaxf(dt, 1e-6f);
        g_minv[node] = 1.0f / fmaxf((float)deg, 1.0f);
    }
}

// ---------------- phase 3a: build split B tiles (linear layout) -------------
// tile kb: B[n][k] = Wcombined[o=n][kk=kb*64+k]
__global__ void k_buildB(const float* __restrict__ Wmsg,
                         const float* __restrict__ Wroot) {
    int idx = blockIdx.x * blockDim.x + threadIdx.x;
    if (idx < NKB * 8192) {
        int kb  = idx >> 13;
        int rem = idx & 8191;
        int n   = rem >> 6;
        int k   = rem & 63;
        int kk  = kb * 64 + k;
        float v = (kk < 1152) ? Wmsg[(size_t)n * 1152 + kk]
                              : Wroot[(size_t)n * C + (kk - 1152)];
        __nv_bfloat16 hi = __float2bfloat16_rn(v);
        __nv_bfloat16 lo = __float2bfloat16_rn(v - __bfloat162float(hi));
        g_Bhi[idx] = hi;
        g_Blo[idx] = lo;
    }
}

// ---------------- phase 3b: mma.sync bf16 GEMM ----------------
// out[m,n] = sum_k Agen[m,k]*Bt[k,n] + bias
// split-bf16: acc += Ahi*Bhi + Ahi*Blo + Alo*Bhi (fp32 accum)
#define LDT 72                 // padded SMEM row stride (bf16 elements)
#define SM_BIAS 0
#define SM_AHI  512
#define SM_ALO  (SM_AHI + 128 * LDT * 2)
#define SM_BHI  (SM_ALO + 128 * LDT * 2)
#define SM_BLO  (SM_BHI + 128 * LDT * 2)
#define SM_TOTAL (SM_BLO + 128 * LDT * 2)

__device__ __forceinline__ void mma16816(float* c, const uint32_t* a, const uint32_t* b) {
    asm volatile(
        "mma.sync.aligned.m16n8k16.row.col.f32.bf16.bf16.f32 "
        "{%0,%1,%2,%3}, {%4,%5,%6,%7}, {%8,%9}, {%0,%1,%2,%3};"
        : "+f"(c[0]), "+f"(c[1]), "+f"(c[2]), "+f"(c[3])
        : "r"(a[0]), "r"(a[1]), "r"(a[2]), "r"(a[3]), "r"(b[0]), "r"(b[1]));
}

__global__ void __launch_bounds__(256)
k_gemm_mma(const float* __restrict__ x,
           const float* __restrict__ bmsg,
           const float* __restrict__ broot,
           float* __restrict__ out) {
    extern __shared__ char smem[];
    float* sBias = (float*)(smem + SM_BIAS);
    __nv_bfloat16* sAhi = (__nv_bfloat16*)(smem + SM_AHI);
    __nv_bfloat16* sAlo = (__nv_bfloat16*)(smem + SM_ALO);
    __nv_bfloat16* sBhi = (__nv_bfloat16*)(smem + SM_BHI);
    __nv_bfloat16* sBlo = (__nv_bfloat16*)(smem + SM_BLO);

    const int tid = threadIdx.x;
    const int wid = tid >> 5;
    const int lid = tid & 31;
    const int m0 = blockIdx.x * 128;

    if (tid < 128) sBias[tid] = bmsg[tid] + broot[tid];

    // A-gen mapping: row r (0..127), half h (32 k-cols)
    const int r = tid >> 1;
    const int h = tid & 1;
    const int m = m0 + r;
    const int mc = min(m, NN - 1);
    const bool valid = (m < NN);
    const float ca = g_amp[mc], ct = g_att[mc], cm = g_minv[mc];

    // warp tiling: 4 m-warps x 2 n-warps; warp tile 32(M) x 64(N)
    const int mw = wid >> 1;
    const int nw = wid & 1;
    const int g  = lid >> 2;       // fragment row group 0..7
    const int tg = lid & 3;        // fragment k/col group 0..3

    float acc[2][8][4];
#pragma unroll
    for (int i = 0; i < 2; i++)
#pragma unroll
        for (int j = 0; j < 8; j++)
#pragma unroll
            for (int q = 0; q < 4; q++) acc[i][j][q] = 0.f;

    for (int kb = 0; kb < NKB; kb++) {
        const int b = kb >> 1;
        const float* base = (b < 6) ? g_Asum : ((b < 9) ? g_Amax : x);
        int sc = (b < 6) ? (b % 3) : ((b < 9) ? (b - 6) : 0);
        float coef = (sc == 0) ? 1.f : ((sc == 1) ? ca : ct);
        if (b >= 3 && b < 6) coef *= cm;
        if (b == 9) coef = 1.f;
        if (!valid) coef = 0.f;

        // ---- generate A tiles (hi & lo), padded stride LDT ----
        {
            const float* p = base + (size_t)mc * C + (kb & 1) * 64 + h * 32;
            int rb = r * LDT + h * 32;
#pragma unroll
            for (int w = 0; w < 8; w++) {
                float4 v = *(const float4*)(p + w * 4);
                float a0 = v.x * coef, a1 = v.y * coef, a2 = v.z * coef, a3 = v.w * coef;
                __nv_bfloat16 h0 = __float2bfloat16_rn(a0);
                __nv_bfloat16 h1 = __float2bfloat16_rn(a1);
                __nv_bfloat16 h2 = __float2bfloat16_rn(a2);
                __nv_bfloat16 h3 = __float2bfloat16_rn(a3);
                __nv_bfloat16 l0 = __float2bfloat16_rn(a0 - __bfloat162float(h0));
                __nv_bfloat16 l1 = __float2bfloat16_rn(a1 - __bfloat162float(h1));
                __nv_bfloat16 l2 = __float2bfloat16_rn(a2 - __bfloat162float(h2));
                __nv_bfloat16 l3 = __float2bfloat16_rn(a3 - __bfloat162float(h3));
                union { __nv_bfloat16 b[2]; uint32_t u; } u0, u1, u2, u3;
                u0.b[0] = h0; u0.b[1] = h1;
                u1.b[0] = h2; u1.b[1] = h3;
                u2.b[0] = l0; u2.b[1] = l1;
                u3.b[0] = l2; u3.b[1] = l3;
                int e = rb + w * 4;
                *(uint32_t*)&sAhi[e]     = u0.u;
                *(uint32_t*)&sAhi[e + 2] = u1.u;
                *(uint32_t*)&sAlo[e]     = u2.u;
                *(uint32_t*)&sAlo[e + 2] = u3.u;
            }
        }
        // ---- copy B tiles (linear global -> padded SMEM) ----
        {
            const __nv_bfloat16* sh = g_Bhi + kb * 8192;
            const __nv_bfloat16* sl = g_Blo + kb * 8192;
#pragma unroll
            for (int it = 0; it < 4; it++) {
                int idx = tid + it * 256;       // 0..1023, each = 8 bf16
                int row = idx >> 3;
                int ch  = idx & 7;
                *(uint4*)&sBhi[row * LDT + ch * 8] = *(const uint4*)&sh[row * 64 + ch * 8];
                *(uint4*)&sBlo[row * LDT + ch * 8] = *(const uint4*)&sl[row * 64 + ch * 8];
            }
        }
        __syncthreads();

        // ---- compute: 4 k16 steps ----
#pragma unroll
        for (int ks = 0; ks < 4; ks++) {
            const int kofs = ks * 16 + 2 * tg;
            uint32_t ahi[2][4], alo[2][4];
#pragma unroll
            for (int i = 0; i < 2; i++) {
                int row = mw * 32 + i * 16 + g;
                ahi[i][0] = *(const uint32_t*)&sAhi[row * LDT + kofs];
                ahi[i][1] = *(const uint32_t*)&sAhi[(row + 8) * LDT + kofs];
                ahi[i][2] = *(const uint32_t*)&sAhi[row * LDT + kofs + 8];
                ahi[i][3] = *(const uint32_t*)&sAhi[(row + 8) * LDT + kofs + 8];
                alo[i][0] = *(const uint32_t*)&sAlo[row * LDT + kofs];
                alo[i][1] = *(const uint32_t*)&sAlo[(row + 8) * LDT + kofs];
                alo[i][2] = *(const uint32_t*)&sAlo[row * LDT + kofs + 8];
                alo[i][3] = *(const uint32_t*)&sAlo[(row + 8) * LDT + kofs + 8];
            }
#pragma unroll
            for (int j = 0; j < 8; j++) {
                int n = nw * 64 + j * 8 + g;
                uint32_t bhi[2], blo[2];
                bhi[0] = *(const uint32_t*)&sBhi[n * LDT + kofs];
                bhi[1] = *(const uint32_t*)&sBhi[n * LDT + kofs + 8];
                blo[0] = *(const uint32_t*)&sBlo[n * LDT + kofs];
                blo[1] = *(const uint32_t*)&sBlo[n * LDT + kofs + 8];
#pragma unroll
                for (int i = 0; i < 2; i++) {
                    mma16816(acc[i][j], ahi[i], bhi);
                    mma16816(acc[i][j], ahi[i], blo);
                    mma16816(acc[i][j], alo[i], bhi);
                }
            }
        }
        __syncthreads();
    }

    // ---- epilogue ----
#pragma unroll
    for (int i = 0; i < 2; i++) {
#pragma unroll
        for (int j = 0; j < 8; j++) {
            int col = nw * 64 + j * 8 + 2 * tg;
            int row0 = m0 + mw * 32 + i * 16 + g;
            int row1 = row0 + 8;
            float bi0 = sBias[col], bi1 = sBias[col + 1];
            if (row0 < NN) {
                float2 v = make_float2(acc[i][j][0] + bi0, acc[i][j][1] + bi1);
                *(float2*)&out[(size_t)row0 * C + col] = v;
            }
            if (row1 < NN) {
                float2 v = make_float2(acc[i][j][2] + bi0, acc[i][j][3] + bi1);
                *(float2*)&out[(size_t)row1 * C + col] = v;
            }
        }
    }
}

// ---------------- launch ----------------
extern "C" void kernel_launch(void* const* d_in, const int* in_sizes, int n_in,
                              void* d_out, int out_size) {
    const float* x     = (const float*)d_in[0];
    const void*  ei    = d_in[1];
    const float* Wmsg  = (const float*)d_in[2];
    const float* bmsg  = (const float*)d_in[3];
    const float* Wroot = (const float*)d_in[4];
    const float* broot = (const float*)d_in[5];
    float*       out   = (float*)d_out;

    cudaFuncSetAttribute(k_gemm_mma, cudaFuncAttributeMaxDynamicSharedMemorySize,
                         SM_TOTAL);

    k_detect<<<1, 32>>>((const int*)ei);
    k_zero_deg<<<(NN + 255) / 256, 256>>>();
    k_count<<<(NE + 255) / 256, 256>>>(ei);
    k_part<<<NB, SB>>>();
    k_scan2<<<1, SB>>>();
    k_write<<<NB, SB>>>();
    k_scatter<<<(NE + 255) / 256, 256>>>(ei);
    k_agg<<<NN, 128>>>(x);
    k_buildB<<<(NKB * 8192 + 255) / 256, 256>>>(Wmsg, Wroot);
    k_gemm_mma<<<(NN + 127) / 128, 256, SM_TOTAL>>>(x, bmsg, broot, out);
}

// round 8
// speedup vs baseline: 3.3720x; 1.2097x over previous
#include <cuda_runtime.h>
#include <cuda_fp16.h>
#include <math.h>
#include <cstdint>

// Problem constants (fixed by the dataset)
#define NN 50000
#define NE 600000
#define C  128
#define KTOT 1280        // 10 blocks of 128: 9 PNA feature blocks + root(x)
#define NKB  (KTOT / 64) // 20 k-blocks of 64

#define SB 256
#define NB ((NN + SB - 1) / SB)

typedef unsigned long long ull;

// ---------------- scratch (device globals: allocation-free rule) -------------
__device__ __align__(16) float g_Asum[(size_t)NN * C];
__device__ __align__(16) float g_Amax[(size_t)NN * C];
__device__ __align__(16) int   g_deg[NN];
__device__ __align__(16) int   g_off[NN + 1];
__device__ __align__(16) int   g_cur[NN];
__device__ __align__(16) int   g_bucket[NE];
__device__ __align__(16) float g_amp[NN];
__device__ __align__(16) float g_att[NN];
__device__ __align__(16) float g_minv[NN];
// fp16 B tiles: [NKB][128 n-rows][64 k-cols], linear
__device__ __align__(16) __half g_B[NKB * 128 * 64];
__device__ __align__(16) int   g_psum[NB];
__device__ __align__(16) float g_plog[NB];
__device__ __align__(16) int   g_pbase[NB];
__device__ float g_ref;
__device__ int   g_is64;

// ---------------- phase 0+1: dtype autodetect + zero degrees ----------------
__global__ void k_zero_deg(const int* __restrict__ ei32) {
    int i = blockIdx.x * blockDim.x + threadIdx.x;
    if (i < NN) g_deg[i] = 0;
    if (i == 0) {
        int odd_or = 0;
        for (int q = 0; q < 128; q++) odd_or |= ei32[2 * q + 1];
        g_is64 = (odd_or == 0) ? 1 : 0;
    }
}

__device__ __forceinline__ int load_edge(const void* ei, int idx) {
    int v;
    if (g_is64) v = (int)((const long long*)ei)[idx];
    else        v = ((const int*)ei)[idx];
    return min(max(v, 0), NN - 1);
}

__global__ void k_count(const void* __restrict__ ei) {
    int i = blockIdx.x * blockDim.x + threadIdx.x;
    if (i < NE) {
        int dst = load_edge(ei, NE + i);
        atomicAdd(&g_deg[dst], 1);
    }
}

// ---------------- multi-block scan ----------------
__global__ void k_part() {
    __shared__ int   si[SB];
    __shared__ float sf[SB];
    int t = threadIdx.x;
    int node = blockIdx.x * SB + t;
    int d = (node < NN) ? g_deg[node] : 0;
    si[t] = d;
    sf[t] = (node < NN) ? log1pf((float)d + 1.0f) : 0.f;
    __syncthreads();
    for (int off = SB / 2; off > 0; off >>= 1) {
        if (t < off) { si[t] += si[t + off]; sf[t] += sf[t + off]; }
        __syncthreads();
    }
    if (t == 0) { g_psum[blockIdx.x] = si[0]; g_plog[blockIdx.x] = sf[0]; }
}

__global__ void k_scan2() {
    __shared__ int   ps[SB];
    __shared__ float ls[SB];
    int t = threadIdx.x;
    int v = (t < NB) ? g_psum[t] : 0;
    float lg = (t < NB) ? g_plog[t] : 0.f;
    ps[t] = v;
    ls[t] = lg;
    __syncthreads();
    for (int off = 1; off < SB; off <<= 1) {
        int a = 0;
        if (t >= off) a = ps[t - off];
        __syncthreads();
        if (t >= off) ps[t] += a;
        __syncthreads();
    }
    if (t < NB) g_pbase[t] = ps[t] - v;
    if (t == SB - 1) g_off[NN] = ps[SB - 1];
    for (int off = SB / 2; off > 0; off >>= 1) {
        if (t < off) ls[t] += ls[t + off];
        __syncthreads();
    }
    if (t == 0) g_ref = fmaxf(ls[0] / (float)NN, 1.0f);
}

__global__ void k_write() {
    __shared__ int ps[SB];
    int t = threadIdx.x;
    int node = blockIdx.x * SB + t;
    int d = (node < NN) ? g_deg[node] : 0;
    ps[t] = d;
    __syncthreads();
    for (int off = 1; off < SB; off <<= 1) {
        int a = 0;
        if (t >= off) a = ps[t - off];
        __syncthreads();
        if (t >= off) ps[t] += a;
        __syncthreads();
    }
    if (node < NN) {
        int off = g_pbase[blockIdx.x] + ps[t] - d;
        g_off[node] = off;
        g_cur[node] = off;
    }
}

__global__ void k_scatter(const void* __restrict__ ei) {
    int i = blockIdx.x * blockDim.x + threadIdx.x;
    if (i < NE) {
        int src = load_edge(ei, i);
        int dst = load_edge(ei, NE + i);
        int pos = atomicAdd(&g_cur[dst], 1);
        if (pos >= 0 && pos < NE) g_bucket[pos] = src;
    }
}

// ---------------- phase 2: per-node gather-reduce (sum + max) ----------------
__global__ void k_agg(const float* __restrict__ x) {
    int node = blockIdx.x;
    int t = threadIdx.x;
    int beg = g_off[node], end = g_off[node + 1];
    int deg = end - beg;
    __shared__ int lst[128];
    float s = 0.f;
    float mx = -1e30f;
    for (int base = beg; base < end; base += 128) {
        int cnt = min(128, end - base);
        if (t < cnt) lst[t] = g_bucket[base + t];
        __syncthreads();
        int j = 0;
        for (; j + 4 <= cnt; j += 4) {
            float v0 = x[(size_t)lst[j + 0] * C + t];
            float v1 = x[(size_t)lst[j + 1] * C + t];
            float v2 = x[(size_t)lst[j + 2] * C + t];
            float v3 = x[(size_t)lst[j + 3] * C + t];
            s += v0 + v1 + v2 + v3;
            mx = fmaxf(mx, fmaxf(fmaxf(v0, v1), fmaxf(v2, v3)));
        }
        for (; j < cnt; j++) {
            float v = x[(size_t)lst[j] * C + t];
            s += v;
            mx = fmaxf(mx, v);
        }
        __syncthreads();
    }
    size_t o = (size_t)node * C + t;
    g_Asum[o] = s;
    g_Amax[o] = (deg > 0) ? mx : 0.f;
    if (t == 0) {
        float dt = log1pf((float)deg + 1.0f);
        float rf = g_ref;
        g_amp[node]  = dt / rf;
        g_att[node]  = rf / fmaxf(dt, 1e-6f);
        g_minv[node] = 1.0f / fmaxf((float)deg, 1.0f);
    }
}

// ---------------- phase 3a: build fp16 B tiles (linear layout) --------------
// tile kb: B[n][k] = Wcombined[o=n][kk=kb*64+k]
__global__ void k_buildB(const float* __restrict__ Wmsg,
                         const float* __restrict__ Wroot) {
    int idx = blockIdx.x * blockDim.x + threadIdx.x;
    if (idx < NKB * 8192) {
        int kb  = idx >> 13;
        int rem = idx & 8191;
        int n   = rem >> 6;
        int k   = rem & 63;
        int kk  = kb * 64 + k;
        float v = (kk < 1152) ? Wmsg[(size_t)n * 1152 + kk]
                              : Wroot[(size_t)n * C + (kk - 1152)];
        g_B[idx] = __float2half_rn(v);
    }
}

// ---------------- phase 3b: mma.sync fp16 single-pass GEMM ------------------
// out[m,n] = sum_k Agen[m,k]*Bt[k,n] + bias   (fp16 inputs, fp32 accum)
#define LDT 72                 // padded SMEM row stride (half elements)
#define SM_BIAS 0
#define SM_A  512
#define SM_B_ (SM_A + 128 * LDT * 2)
#define SM_TOTAL (SM_B_ + 128 * LDT * 2)

__device__ __forceinline__ void mma16816(float* c, const uint32_t* a, const uint32_t* b) {
    asm volatile(
        "mma.sync.aligned.m16n8k16.row.col.f32.f16.f16.f32 "
        "{%0,%1,%2,%3}, {%4,%5,%6,%7}, {%8,%9}, {%0,%1,%2,%3};"
        : "+f"(c[0]), "+f"(c[1]), "+f"(c[2]), "+f"(c[3])
        : "r"(a[0]), "r"(a[1]), "r"(a[2]), "r"(a[3]), "r"(b[0]), "r"(b[1]));
}

__global__ void __launch_bounds__(256)
k_gemm_mma(const float* __restrict__ x,
           const float* __restrict__ bmsg,
           const float* __restrict__ broot,
           float* __restrict__ out) {
    extern __shared__ char smem[];
    float*  sBias = (float*)(smem + SM_BIAS);
    __half* sA = (__half*)(smem + SM_A);
    __half* sB = (__half*)(smem + SM_B_);

    const int tid = threadIdx.x;
    const int wid = tid >> 5;
    const int lid = tid & 31;
    const int m0 = blockIdx.x * 128;

    if (tid < 128) sBias[tid] = bmsg[tid] + broot[tid];

    // A-gen mapping: row r (0..127), half h (32 k-cols)
    const int r = tid >> 1;
    const int h = tid & 1;
    const int m = m0 + r;
    const int mc = min(m, NN - 1);
    const bool valid = (m < NN);
    const float ca = g_amp[mc], ct = g_att[mc], cm = g_minv[mc];

    // warp tiling: 4 m-warps x 2 n-warps; warp tile 32(M) x 64(N)
    const int mw = wid >> 1;
    const int nw = wid & 1;
    const int g  = lid >> 2;       // fragment row group 0..7
    const int tg = lid & 3;        // fragment k/col group 0..3

    float acc[2][8][4];
#pragma unroll
    for (int i = 0; i < 2; i++)
#pragma unroll
        for (int j = 0; j < 8; j++)
#pragma unroll
            for (int q = 0; q < 4; q++) acc[i][j][q] = 0.f;

    for (int kb = 0; kb < NKB; kb++) {
        const int b = kb >> 1;
        const float* base = (b < 6) ? g_Asum : ((b < 9) ? g_Amax : x);
        int sc = (b < 6) ? (b % 3) : ((b < 9) ? (b - 6) : 0);
        float coef = (sc == 0) ? 1.f : ((sc == 1) ? ca : ct);
        if (b >= 3 && b < 6) coef *= cm;
        if (b == 9) coef = 1.f;
        if (!valid) coef = 0.f;

        // ---- generate A tile (fp16), padded stride LDT ----
        {
            const float* p = base + (size_t)mc * C + (kb & 1) * 64 + h * 32;
            int rb = r * LDT + h * 32;
#pragma unroll
            for (int w = 0; w < 8; w++) {
                float4 v = *(const float4*)(p + w * 4);
                union { __half b[2]; uint32_t u; } u0, u1;
                u0.b[0] = __float2half_rn(v.x * coef);
                u0.b[1] = __float2half_rn(v.y * coef);
                u1.b[0] = __float2half_rn(v.z * coef);
                u1.b[1] = __float2half_rn(v.w * coef);
                int e = rb + w * 4;
                *(uint32_t*)&sA[e]     = u0.u;
                *(uint32_t*)&sA[e + 2] = u1.u;
            }
        }
        // ---- copy B tile (linear global -> padded SMEM) ----
        {
            const __half* src = g_B + kb * 8192;
#pragma unroll
            for (int it = 0; it < 4; it++) {
                int idx = tid + it * 256;       // 0..1023, each = 8 halfs
                int row = idx >> 3;
                int ch  = idx & 7;
                *(uint4*)&sB[row * LDT + ch * 8] = *(const uint4*)&src[row * 64 + ch * 8];
            }
        }
        __syncthreads();

        // ---- compute: 4 k16 steps ----
#pragma unroll
        for (int ks = 0; ks < 4; ks++) {
            const int kofs = ks * 16 + 2 * tg;
            uint32_t a[2][4];
#pragma unroll
            for (int i = 0; i < 2; i++) {
                int row = mw * 32 + i * 16 + g;
                a[i][0] = *(const uint32_t*)&sA[row * LDT + kofs];
                a[i][1] = *(const uint32_t*)&sA[(row + 8) * LDT + kofs];
                a[i][2] = *(const uint32_t*)&sA[row * LDT + kofs + 8];
                a[i][3] = *(const uint32_t*)&sA[(row + 8) * LDT + kofs + 8];
            }
#pragma unroll
            for (int j = 0; j < 8; j++) {
                int n = nw * 64 + j * 8 + g;
                uint32_t bb[2];
                bb[0] = *(const uint32_t*)&sB[n * LDT + kofs];
                bb[1] = *(const uint32_t*)&sB[n * LDT + kofs + 8];
#pragma unroll
                for (int i = 0; i < 2; i++)
                    mma16816(acc[i][j], a[i], bb);
            }
        }
        __syncthreads();
    }

    // ---- epilogue ----
#pragma unroll
    for (int i = 0; i < 2; i++) {
#pragma unroll
        for (int j = 0; j < 8; j++) {
            int col = nw * 64 + j * 8 + 2 * tg;
            int row0 = m0 + mw * 32 + i * 16 + g;
            int row1 = row0 + 8;
            float bi0 = sBias[col], bi1 = sBias[col + 1];
            if (row0 < NN) {
                float2 v = make_float2(acc[i][j][0] + bi0, acc[i][j][1] + bi1);
                *(float2*)&out[(size_t)row0 * C + col] = v;
            }
            if (row1 < NN) {
                float2 v = make_float2(acc[i][j][2] + bi0, acc[i][j][3] + bi1);
                *(float2*)&out[(size_t)row1 * C + col] = v;
            }
        }
    }
}

// ---------------- launch ----------------
extern "C" void kernel_launch(void* const* d_in, const int* in_sizes, int n_in,
                              void* d_out, int out_size) {
    const float* x     = (const float*)d_in[0];
    const void*  ei    = d_in[1];
    const float* Wmsg  = (const float*)d_in[2];
    const float* bmsg  = (const float*)d_in[3];
    const float* Wroot = (const float*)d_in[4];
    const float* broot = (const float*)d_in[5];
    float*       out   = (float*)d_out;

    cudaFuncSetAttribute(k_gemm_mma, cudaFuncAttributeMaxDynamicSharedMemorySize,
                         SM_TOTAL);

    k_zero_deg<<<(NN + 255) / 256, 256>>>((const int*)ei);
    k_count<<<(NE + 255) / 256, 256>>>(ei);
    k_part<<<NB, SB>>>();
    k_scan2<<<1, SB>>>();
    k_write<<<NB, SB>>>();
    k_scatter<<<(NE + 255) / 256, 256>>>(ei);
    k_agg<<<NN, 128>>>(x);
    k_buildB<<<(NKB * 8192 + 255) / 256, 256>>>(Wmsg, Wroot);
    k_gemm_mma<<<(NN + 127) / 128, 256, SM_TOTAL>>>(x, bmsg, broot, out);
}

// round 9
// speedup vs baseline: 5.8906x; 1.7469x over previous
#include <cuda_runtime.h>
#include <cuda_fp16.h>
#include <math.h>
#include <cstdint>

// Problem constants (fixed by the dataset)
#define NN 50000
#define NE 600000
#define C  128

#define SB 256
#define NB ((NN + SB - 1) / SB)

// ---------------- scratch (device globals: allocation-free rule) -------------
__device__ __align__(16) float g_Asum[(size_t)NN * C];
__device__ __align__(16) float g_Amax[(size_t)NN * C];
__device__ __align__(16) int   g_deg[NN];
__device__ __align__(16) int   g_off[NN + 1];
__device__ __align__(16) int   g_cur[NN];
__device__ __align__(16) int   g_bucket[NE];
__device__ __align__(16) float g_amp[NN];
__device__ __align__(16) float g_att[NN];
__device__ __align__(16) float g_minv[NN];
// fp16 B tiles: [s(3)][kb(8)][n(128)][k(64)]; root stored at s=0, kb=6,7
__device__ __align__(16) __half g_B2[3 * 8 * 128 * 64];
__device__ __align__(16) int   g_psum[NB];
__device__ __align__(16) float g_plog[NB];
__device__ __align__(16) int   g_pbase[NB];
__device__ float g_ref;
__device__ int   g_is64;

// ---------------- phase 0+1: dtype autodetect + zero degrees ----------------
__global__ void k_zero_deg(const int* __restrict__ ei32) {
    int i = blockIdx.x * blockDim.x + threadIdx.x;
    if (i < NN) g_deg[i] = 0;
    if (i == 0) {
        int odd_or = 0;
        for (int q = 0; q < 128; q++) odd_or |= ei32[2 * q + 1];
        g_is64 = (odd_or == 0) ? 1 : 0;
    }
}

__device__ __forceinline__ int load_edge(const void* ei, int idx) {
    int v;
    if (g_is64) v = (int)((const long long*)ei)[idx];
    else        v = ((const int*)ei)[idx];
    return min(max(v, 0), NN - 1);
}

__global__ void k_count(const void* __restrict__ ei) {
    int i = blockIdx.x * blockDim.x + threadIdx.x;
    if (i < NE) {
        int dst = load_edge(ei, NE + i);
        atomicAdd(&g_deg[dst], 1);
    }
}

// ---------------- multi-block scan ----------------
__global__ void k_part() {
    __shared__ int   si[SB];
    __shared__ float sf[SB];
    int t = threadIdx.x;
    int node = blockIdx.x * SB + t;
    int d = (node < NN) ? g_deg[node] : 0;
    si[t] = d;
    sf[t] = (node < NN) ? log1pf((float)d + 1.0f) : 0.f;
    __syncthreads();
    for (int off = SB / 2; off > 0; off >>= 1) {
        if (t < off) { si[t] += si[t + off]; sf[t] += sf[t + off]; }
        __syncthreads();
    }
    if (t == 0) { g_psum[blockIdx.x] = si[0]; g_plog[blockIdx.x] = sf[0]; }
}

__global__ void k_scan2() {
    __shared__ int   ps[SB];
    __shared__ float ls[SB];
    int t = threadIdx.x;
    int v = (t < NB) ? g_psum[t] : 0;
    float lg = (t < NB) ? g_plog[t] : 0.f;
    ps[t] = v;
    ls[t] = lg;
    __syncthreads();
    for (int off = 1; off < SB; off <<= 1) {
        int a = 0;
        if (t >= off) a = ps[t - off];
        __syncthreads();
        if (t >= off) ps[t] += a;
        __syncthreads();
    }
    if (t < NB) g_pbase[t] = ps[t] - v;
    if (t == SB - 1) g_off[NN] = ps[SB - 1];
    for (int off = SB / 2; off > 0; off >>= 1) {
        if (t < off) ls[t] += ls[t + off];
        __syncthreads();
    }
    if (t == 0) g_ref = fmaxf(ls[0] / (float)NN, 1.0f);
}

__global__ void k_write() {
    __shared__ int ps[SB];
    int t = threadIdx.x;
    int node = blockIdx.x * SB + t;
    int d = (node < NN) ? g_deg[node] : 0;
    ps[t] = d;
    __syncthreads();
    for (int off = 1; off < SB; off <<= 1) {
        int a = 0;
        if (t >= off) a = ps[t - off];
        __syncthreads();
        if (t >= off) ps[t] += a;
        __syncthreads();
    }
    if (node < NN) {
        int off = g_pbase[blockIdx.x] + ps[t] - d;
        g_off[node] = off;
        g_cur[node] = off;
    }
}

__global__ void k_scatter(const void* __restrict__ ei) {
    int i = blockIdx.x * blockDim.x + threadIdx.x;
    if (i < NE) {
        int src = load_edge(ei, i);
        int dst = load_edge(ei, NE + i);
        int pos = atomicAdd(&g_cur[dst], 1);
        if (pos >= 0 && pos < NE) g_bucket[pos] = src;
    }
}

// ---------------- phase 2: warp-per-node gather-reduce (sum + max) ----------
__global__ void __launch_bounds__(256)
k_agg(const float* __restrict__ x) {
    int wid = threadIdx.x >> 5;
    int lane = threadIdx.x & 31;
    int node = blockIdx.x * 8 + wid;
    if (node >= NN) return;
    int beg = g_off[node], end = g_off[node + 1];
    int deg = end - beg;
    int c0 = lane * 4;

    float4 s = make_float4(0.f, 0.f, 0.f, 0.f);
    float4 mx = make_float4(-1e30f, -1e30f, -1e30f, -1e30f);

    int e = beg;
    for (; e + 4 <= end; e += 4) {
        int i0 = g_bucket[e];
        int i1 = g_bucket[e + 1];
        int i2 = g_bucket[e + 2];
        int i3 = g_bucket[e + 3];
        float4 v0 = *(const float4*)&x[(size_t)i0 * C + c0];
        float4 v1 = *(const float4*)&x[(size_t)i1 * C + c0];
        float4 v2 = *(const float4*)&x[(size_t)i2 * C + c0];
        float4 v3 = *(const float4*)&x[(size_t)i3 * C + c0];
        s.x += (v0.x + v1.x) + (v2.x + v3.x);
        s.y += (v0.y + v1.y) + (v2.y + v3.y);
        s.z += (v0.z + v1.z) + (v2.z + v3.z);
        s.w += (v0.w + v1.w) + (v2.w + v3.w);
        mx.x = fmaxf(mx.x, fmaxf(fmaxf(v0.x, v1.x), fmaxf(v2.x, v3.x)));
        mx.y = fmaxf(mx.y, fmaxf(fmaxf(v0.y, v1.y), fmaxf(v2.y, v3.y)));
        mx.z = fmaxf(mx.z, fmaxf(fmaxf(v0.z, v1.z), fmaxf(v2.z, v3.z)));
        mx.w = fmaxf(mx.w, fmaxf(fmaxf(v0.w, v1.w), fmaxf(v2.w, v3.w)));
    }
    for (; e < end; e++) {
        int i0 = g_bucket[e];
        float4 v0 = *(const float4*)&x[(size_t)i0 * C + c0];
        s.x += v0.x; s.y += v0.y; s.z += v0.z; s.w += v0.w;
        mx.x = fmaxf(mx.x, v0.x); mx.y = fmaxf(mx.y, v0.y);
        mx.z = fmaxf(mx.z, v0.z); mx.w = fmaxf(mx.w, v0.w);
    }
    if (deg == 0) mx = make_float4(0.f, 0.f, 0.f, 0.f);
    *(float4*)&g_Asum[(size_t)node * C + c0] = s;
    *(float4*)&g_Amax[(size_t)node * C + c0] = mx;
    if (lane == 0) {
        float dt = log1pf((float)deg + 1.0f);
        float rf = g_ref;
        g_amp[node]  = dt / rf;
        g_att[node]  = rf / fmaxf(dt, 1e-6f);
        g_minv[node] = 1.0f / fmaxf((float)deg, 1.0f);
    }
}

// ---------------- phase 3a: build fp16 B tiles -------------------------------
// layout: [s][kb][n][k]. For kb<6: K-group kk=kb*64+k in [0,384);
//   seg=kk/128 (0:Asum 1:Amean 2:Amax), col=kk%128, block j=seg*3+s,
//   value = Wmsg[n, j*128+col]. kb 6,7 (s=0 only): Wroot[n, (kb-6)*64+k].
__global__ void k_buildB(const float* __restrict__ Wmsg,
                         const float* __restrict__ Wroot) {
    int idx = blockIdx.x * blockDim.x + threadIdx.x;
    if (idx < 3 * 8 * 8192) {
        int s   = idx / 65536;
        int rem = idx - s * 65536;
        int kb  = rem >> 13;
        int r2  = rem & 8191;
        int n   = r2 >> 6;
        int k   = r2 & 63;
        float v = 0.f;
        if (kb < 6) {
            int kk  = kb * 64 + k;
            int seg = kk >> 7;
            int col = kk & 127;
            int j   = seg * 3 + s;
            v = Wmsg[(size_t)n * 1152 + j * 128 + col];
        } else if (s == 0) {
            int col = (kb - 6) * 64 + k;
            v = Wroot[(size_t)n * 128 + col];
        }
        g_B2[idx] = __float2half_rn(v);
    }
}

// ---------------- phase 3b: staged-A mma.sync GEMM ---------------------------
// A2 = [Asum | Amean | Amax | x] staged fp16 in SMEM once per CTA (8 blocks of
// 64x64). 3 scaler groups reuse the A panel; amp/att applied in fp32 merge.
#define LDT 72
#define ABLK_B (64 * LDT * 2)             // 9216 bytes per A block
#define SM_BIAS 0
#define SM_A    512
#define SM_B    (SM_A + 8 * ABLK_B)       // 74240
#define SM_TOTAL (SM_B + 128 * LDT * 2)   // 92672

__device__ __forceinline__ void mma16816(float* c, const uint32_t* a, const uint32_t* b) {
    asm volatile(
        "mma.sync.aligned.m16n8k16.row.col.f32.f16.f16.f32 "
        "{%0,%1,%2,%3}, {%4,%5,%6,%7}, {%8,%9}, {%0,%1,%2,%3};"
        : "+f"(c[0]), "+f"(c[1]), "+f"(c[2]), "+f"(c[3])
        : "r"(a[0]), "r"(a[1]), "r"(a[2]), "r"(a[3]), "r"(b[0]), "r"(b[1]));
}

__device__ __forceinline__ void ldsm4(uint32_t* r, uint32_t addr) {
    asm volatile("ldmatrix.sync.aligned.m8n8.x4.shared.b16 {%0,%1,%2,%3}, [%4];"
                 : "=r"(r[0]), "=r"(r[1]), "=r"(r[2]), "=r"(r[3]) : "r"(addr));
}

__device__ __forceinline__ void do_mma_block(float acc[2][4][4],
                                             uint32_t aA0, uint32_t aA1,
                                             uint32_t bA0, uint32_t bA1) {
#pragma unroll
    for (int ks = 0; ks < 4; ks++) {
        uint32_t a0[4], a1[4], b0[4], b1[4];
        ldsm4(a0, aA0 + ks * 32);
        ldsm4(a1, aA1 + ks * 32);
        ldsm4(b0, bA0 + ks * 32);
        ldsm4(b1, bA1 + ks * 32);
        mma16816(acc[0][0], a0, &b0[0]);
        mma16816(acc[0][1], a0, &b0[2]);
        mma16816(acc[0][2], a0, &b1[0]);
        mma16816(acc[0][3], a0, &b1[2]);
        mma16816(acc[1][0], a1, &b0[0]);
        mma16816(acc[1][1], a1, &b0[2]);
        mma16816(acc[1][2], a1, &b1[0]);
        mma16816(acc[1][3], a1, &b1[2]);
    }
}

__global__ void __launch_bounds__(256, 2)
k_gemm_mma(const float* __restrict__ x,
           const float* __restrict__ bmsg,
           const float* __restrict__ broot,
           float* __restrict__ out) {
    extern __shared__ char smem[];
    float*  sBias = (float*)(smem + SM_BIAS);
    __half* sA = (__half*)(smem + SM_A);
    __half* sB = (__half*)(smem + SM_B);

    const int tid = threadIdx.x;
    const int wid = tid >> 5;
    const int lid = tid & 31;
    const int m0 = blockIdx.x * 64;

    if (tid < 128) sBias[tid] = bmsg[tid] + broot[tid];

    // ---- stage A panel: 8 blocks of 64 rows x 64 k-cols ----
    {
        const int r = tid >> 2;
        const int q = tid & 3;
        const int m = m0 + r;
        const int mc = min(m, NN - 1);
        const bool valid = (m < NN);
        const float minv = g_minv[mc];
#pragma unroll
        for (int blk = 0; blk < 8; blk++) {
            const float* base;
            float coef;
            if (blk < 2)      { base = g_Asum; coef = 1.f; }
            else if (blk < 4) { base = g_Asum; coef = minv; }
            else if (blk < 6) { base = g_Amax; coef = 1.f; }
            else              { base = x;      coef = 1.f; }
            if (!valid) coef = 0.f;
            const float* p = base + (size_t)mc * C + (blk & 1) * 64 + q * 16;
            __half* dst = sA + blk * (64 * LDT) + r * LDT + q * 16;
#pragma unroll
            for (int w = 0; w < 4; w++) {
                float4 v = *(const float4*)(p + w * 4);
                __half2 h0 = __float22half2_rn(make_float2(v.x * coef, v.y * coef));
                __half2 h1 = __float22half2_rn(make_float2(v.z * coef, v.w * coef));
                *(__half2*)(dst + w * 4)     = h0;
                *(__half2*)(dst + w * 4 + 2) = h1;
            }
        }
    }

    // warp tiling: 2 m-warps x 4 n-warps; warp tile 32(M) x 32(N)
    const int mw = wid >> 2;
    const int nw = wid & 3;
    const int g  = lid >> 2;
    const int tg = lid & 3;

    // ldmatrix lane addressing (matches R8-verified scalar fragment layout)
    const int arow0 = mw * 32 + (lid & 7) + (lid & 8);
    const int acol  = ((lid & 16) >> 1);           // 0 or 8 halfs
    uint32_t aA0 = (uint32_t)__cvta_generic_to_shared(
        sA + (arow0 + 0)  * LDT + acol);
    uint32_t aA1 = (uint32_t)__cvta_generic_to_shared(
        sA + (arow0 + 16) * LDT + acol);

    const int brow0 = nw * 32 + ((lid & 16) >> 1) + (lid & 7);
    const int bcol  = (lid & 8);                   // 0 or 8 halfs
    uint32_t bA0 = (uint32_t)__cvta_generic_to_shared(sB + (brow0 + 0)  * LDT + bcol);
    uint32_t bA1 = (uint32_t)__cvta_generic_to_shared(sB + (brow0 + 16) * LDT + bcol);

    float accF[2][4][4];
#pragma unroll
    for (int i = 0; i < 2; i++)
#pragma unroll
        for (int j = 0; j < 4; j++)
#pragma unroll
            for (int q = 0; q < 4; q++) accF[i][j][q] = 0.f;

    __syncthreads();

    // ---- 3 scaler groups over shared A panel ----
    for (int s = 0; s < 3; s++) {
        float accW[2][4][4];
#pragma unroll
        for (int i = 0; i < 2; i++)
#pragma unroll
            for (int j = 0; j < 4; j++)
#pragma unroll
                for (int q = 0; q < 4; q++) accW[i][j][q] = 0.f;

        for (int kb = 0; kb < 6; kb++) {
            // load B tile [128][64] -> padded SMEM
            const __half* src = g_B2 + (size_t)(s * 8 + kb) * 8192;
#pragma unroll
            for (int it = 0; it < 4; it++) {
                int idx = tid + it * 256;
                int row = idx >> 3;
                int ch  = idx & 7;
                *(uint4*)&sB[row * LDT + ch * 8] = *(const uint4*)&src[row * 64 + ch * 8];
            }
            __syncthreads();
            uint32_t ab = (uint32_t)(kb * ABLK_B);
            do_mma_block(accW, aA0 + ab, aA1 + ab, bA0, bA1);
            __syncthreads();
        }

        // merge: accF += coef(row) * accW   (fp32, exact)
        if (s == 0) {
#pragma unroll
            for (int i = 0; i < 2; i++)
#pragma unroll
                for (int j = 0; j < 4; j++)
#pragma unroll
                    for (int q = 0; q < 4; q++) accF[i][j][q] += accW[i][j][q];
        } else {
            const float* carr = (s == 1) ? g_amp : g_att;
#pragma unroll
            for (int i = 0; i < 2; i++) {
                int r0 = min(m0 + mw * 32 + i * 16 + g,     NN - 1);
                int r1 = min(m0 + mw * 32 + i * 16 + g + 8, NN - 1);
                float cf0 = carr[r0];
                float cf1 = carr[r1];
#pragma unroll
                for (int j = 0; j < 4; j++) {
                    accF[i][j][0] += cf0 * accW[i][j][0];
                    accF[i][j][1] += cf0 * accW[i][j][1];
                    accF[i][j][2] += cf1 * accW[i][j][2];
                    accF[i][j][3] += cf1 * accW[i][j][3];
                }
            }
        }
    }

    // ---- root blocks (x @ Wroot^T), no scaler: accumulate into accF ----
    for (int kb = 6; kb < 8; kb++) {
        const __half* src = g_B2 + (size_t)kb * 8192;   // s=0 region
#pragma unroll
        for (int it = 0; it < 4; it++) {
            int idx = tid + it * 256;
            int row = idx >> 3;
            int ch  = idx & 7;
            *(uint4*)&sB[row * LDT + ch * 8] = *(const uint4*)&src[row * 64 + ch * 8];
        }
        __syncthreads();
        uint32_t ab = (uint32_t)(kb * ABLK_B);
        do_mma_block(accF, aA0 + ab, aA1 + ab, bA0, bA1);
        __syncthreads();
    }

    // ---- epilogue ----
#pragma unroll
    for (int i = 0; i < 2; i++) {
#pragma unroll
        for (int j = 0; j < 4; j++) {
            int col  = nw * 32 + j * 8 + 2 * tg;
            int row0 = m0 + mw * 32 + i * 16 + g;
            int row1 = row0 + 8;
            float bi0 = sBias[col], bi1 = sBias[col + 1];
            if (row0 < NN) {
                float2 v = make_float2(accF[i][j][0] + bi0, accF[i][j][1] + bi1);
                *(float2*)&out[(size_t)row0 * C + col] = v;
            }
            if (row1 < NN) {
                float2 v = make_float2(accF[i][j][2] + bi0, accF[i][j][3] + bi1);
                *(float2*)&out[(size_t)row1 * C + col] = v;
            }
        }
    }
}

// ---------------- launch ----------------
extern "C" void kernel_launch(void* const* d_in, const int* in_sizes, int n_in,
                              void* d_out, int out_size) {
    const float* x     = (const float*)d_in[0];
    const void*  ei    = d_in[1];
    const float* Wmsg  = (const float*)d_in[2];
    const float* bmsg  = (const float*)d_in[3];
    const float* Wroot = (const float*)d_in[4];
    const float* broot = (const float*)d_in[5];
    float*       out   = (float*)d_out;

    cudaFuncSetAttribute(k_gemm_mma, cudaFuncAttributeMaxDynamicSharedMemorySize,
                         SM_TOTAL);

    k_zero_deg<<<(NN + 255) / 256, 256>>>((const int*)ei);
    k_count<<<(NE + 255) / 256, 256>>>(ei);
    k_part<<<NB, SB>>>();
    k_scan2<<<1, SB>>>();
    k_write<<<NB, SB>>>();
    k_scatter<<<(NE + 255) / 256, 256>>>(ei);
    k_agg<<<(NN + 7) / 8, 256>>>(x);
    k_buildB<<<(3 * 8 * 8192 + 255) / 256, 256>>>(Wmsg, Wroot);
    k_gemm_mma<<<(NN + 63) / 64, 256, SM_TOTAL>>>(x, bmsg, broot, out);
}